// round 6
// baseline (speedup 1.0000x reference)
#include <cuda_runtime.h>
#include <cuda_bf16.h>
#include <cuda_fp16.h>

// emb[b,f,e] = b2[f,e] + sum_h W2[f,e,h]*relu(x[b,f]*W1[f,h]+b1[f,h])
// Piecewise-linear-in-x: per f, 65 segments; emb = A(seg)*x + C(seg).
// fp16 segment row (64B): 8 x {half2 A, half2 C}.

#define BN 16384
#define FN 128
#define HN 64
#define EN 16
#define TAB_S 524       // smem table stride in h4 units

struct __align__(8) h4 { __half2 a, c; };

__device__ h4    g_tab_h[FN * 520];   // per f: 65 segs * 8 h4
__device__ float g_thr[FN * 64];      // sorted hinge thresholds per f

// ---------------------------------------------------------------------------
// Kernel 1: per-feature precompute. One block per f, 128 threads.
// ---------------------------------------------------------------------------
__global__ void __launch_bounds__(128) dfe_precompute(
    const float* __restrict__ W1, const float* __restrict__ b1,
    const float* __restrict__ W2, const float* __restrict__ b2)
{
    int f = blockIdx.x;
    int tid = threadIdx.x;

    __shared__ float sw[HN], sb[HN], tv_[HN], st[HN];
    __shared__ int   sidx[HN];
    __shared__ float sv[EN * HN];
    __shared__ float stab[65 * 32];

    for (int i = tid; i < EN * HN; i += 128) sv[i] = W2[f * EN * HN + i];

    if (tid < HN) {
        float w = W1[f * HN + tid];
        float b = b1[f * HN + tid];
        sw[tid] = w; sb[tid] = b;
        tv_[tid] = (w != 0.0f) ? (-b / w) : 3.0e38f;  // sentinel: never crossed
    }
    __syncthreads();

    // stable rank-sort of 64 thresholds
    if (tid < HN) {
        float tv = tv_[tid];
        int r = 0;
        for (int j = 0; j < HN; j++) {
            float tj = tv_[j];
            r += (tj < tv) || (tj == tv && j < tid);
        }
        st[r] = tv;
        sidx[r] = tid;
    }
    __syncthreads();

    if (tid < HN) g_thr[f * HN + tid] = st[tid];

    // segment walk: 16 threads, one per e (all operands in smem)
    if (tid < EN) {
        int e = tid;
        const float* w2 = sv + e * HN;
        float A = 0.0f;
        float C = b2[f * EN + e];
        for (int h = 0; h < HN; h++) {
            float w = sw[h], b = sb[h], v = w2[h];
            float m = (w < 0.0f) ? 1.0f : 0.0f;            // active at x=-inf
            A += m * w * v;
            C += m * b * v;
            C += (w == 0.0f) ? fmaxf(b, 0.0f) * v : 0.0f;  // constant hinge
        }
        int grp = e >> 1, par = e & 1;
        for (int s = 0; s <= 64; s++) {
            stab[s * 32 + grp * 4 + par]     = A;
            stab[s * 32 + grp * 4 + 2 + par] = C;
            if (s < 64) {
                int h = sidx[s];
                float w = sw[h], b = sb[h], v = w2[h];
                float sg = (w > 0.0f) ? 1.0f : ((w < 0.0f) ? -1.0f : 0.0f);
                A += sg * w * v;
                C += sg * b * v;
            }
        }
    }
    __syncthreads();

    // pack fp32 staging -> fp16 table, coalesced writeback
    for (int i = tid; i < 520; i += 128) {
        int s = i >> 3, j = i & 7;
        const float* p = stab + s * 32 + j * 4;
        h4 v;
        v.a = __floats2half2_rn(p[0], p[1]);
        v.c = __floats2half2_rn(p[2], p[3]);
        g_tab_h[f * 520 + i] = v;
    }
}

// ---------------------------------------------------------------------------
// Kernel 2: evaluation. Block = 4 features ("quad") x 512 rows, 256 threads.
// Warp owns 64 rows as 8 batches of 8.
// Phase 1: lane=(ff=lane>>3, rrow=lane&7): 32 distinct searches.
//   Search: 3 scalar levels then exact 8-wide window count (2x LDS.128) over
//   bank-partitioned thresholds slot(t) = (t>>3)*32 + ff*8 + (t&7).
// Phase 2: lane=(r01=lane>>4, ff2=(lane>>2)&3, j4=lane&3): 4 passes of 2 rows;
//   per pass: broadcast LDS.64 of (xs,seg), LDS.128 table chunk, 4 FMA,
//   STG.128 (coalesced 256B per row).
// ---------------------------------------------------------------------------
__global__ void __launch_bounds__(256, 8) dfe_eval(
    const float* __restrict__ x, float* __restrict__ out)
{
    __shared__ h4     stab[4 * TAB_S];
    __shared__ float  sthr[8 * 32];    // bank-partitioned: [(t>>3)*32 + ff*8 + (t&7)]
    __shared__ float2 sxch[8][32];     // per-warp (xs, seg) exchange

    int tid = threadIdx.x;
    int quad = blockIdx.x;
    int bbase = blockIdx.y * 512;

    #pragma unroll
    for (int ff = 0; ff < 4; ff++)
        for (int i = tid; i < 520; i += 256)
            stab[ff * TAB_S + i] = g_tab_h[(quad * 4 + ff) * 520 + i];
    for (int i = tid; i < 4 * 64; i += 256) {
        int ff = i >> 6, t = i & 63;
        sthr[(t >> 3) * 32 + ff * 8 + (t & 7)] = g_thr[quad * 256 + i];
    }
    __syncthreads();

    int lane = tid & 31, w = tid >> 5;
    int rrow = lane & 7;            // phase-1 row within batch
    int ff   = lane >> 3;           // phase-1 feature
    int r01  = lane >> 4;           // phase-2 row parity
    int ff2  = (lane >> 2) & 3;     // phase-2 feature
    int j4   = lane & 3;            // phase-2 e-quad

    const float* thrb = sthr + ff * 8;          // phase-1 threshold base (bank-partitioned)
    const h4*    tabf = stab + ff2 * TAB_S;     // phase-2 table
    float2*      xch  = sxch[w];

    int rb0 = bbase + w * 64;
    const float* xpb  = x   + (size_t)rb0 * FN + quad * 4 + ff;
    float*       outb = out + (size_t)rb0 * (FN * EN) + quad * 64 + ff2 * 16 + j4 * 4;

    // search: 3 scalar levels + exact 8-window count
    auto seg_search = [&](float xs) -> int {
        int p = (thrb[3 * 32 + 7] <= xs) ? 32 : 0;                       // t=31
        p += (thrb[((p + 15) >> 3) * 32 + 7] <= xs) ? 16 : 0;            // t=p+15
        p += (thrb[((p + 7) >> 3) * 32 + 7] <= xs) ? 8 : 0;              // t=p+7
        const float4* wnd = (const float4*)(thrb + (p >> 3) * 32);
        float4 w0 = wnd[0], w1 = wnd[1];
        int c = (w0.x <= xs) + (w0.y <= xs) + (w0.z <= xs) + (w0.w <= xs)
              + (w1.x <= xs) + (w1.y <= xs) + (w1.z <= xs) + (w1.w <= xs);
        return p + c;   // exact count in [0,64]
    };

    float xs = __ldg(xpb + (size_t)rrow * FN);
    int   seg = seg_search(xs);

    #pragma unroll
    for (int batch = 0; batch < 8; batch++) {
        xch[lane] = make_float2(xs, __int_as_float(seg));
        __syncwarp();
        if (batch < 7)
            xs = __ldg(xpb + (size_t)((batch + 1) * 8 + rrow) * FN);

        float* orow = outb + (size_t)(batch * 8) * (FN * EN);
        #pragma unroll
        for (int k = 0; k < 4; k++) {
            int row = k * 2 + r01;
            float2 e = xch[ff2 * 8 + row];      // broadcast across 4 j4 lanes
            int sg = __float_as_int(e.y);
            // 16B table chunk: e-pairs (2*j4, 2*j4+1)
            const h4* tp = tabf + sg * 8 + j4 * 2;
            h4 v0 = tp[0], v1 = tp[1];
            float2 a0 = __half22float2(v0.a), c0 = __half22float2(v0.c);
            float2 a1 = __half22float2(v1.a), c1 = __half22float2(v1.c);
            float4 o;
            o.x = fmaf(a0.x, e.x, c0.x);
            o.y = fmaf(a0.y, e.x, c0.y);
            o.z = fmaf(a1.x, e.x, c1.x);
            o.w = fmaf(a1.y, e.x, c1.y);
            __stcs((float4*)(orow + (size_t)row * (FN * EN)), o);
        }

        if (batch < 7) seg = seg_search(xs);
        __syncwarp();   // protect xch before next overwrite
    }
}

extern "C" void kernel_launch(void* const* d_in, const int* in_sizes, int n_in,
                              void* d_out, int out_size)
{
    const float* x  = (const float*)d_in[0];
    const float* W1 = (const float*)d_in[1];
    const float* b1 = (const float*)d_in[2];
    const float* W2 = (const float*)d_in[3];
    const float* b2 = (const float*)d_in[4];
    float* out = (float*)d_out;

    dfe_precompute<<<FN, 128>>>(W1, b1, W2, b2);
    dfe_eval<<<dim3(FN / 4, BN / 512), 256>>>(x, out);
}

// round 7
// speedup vs baseline: 1.0398x; 1.0398x over previous
#include <cuda_runtime.h>
#include <cuda_bf16.h>
#include <cuda_fp16.h>

// emb[b,f,e] = b2[f,e] + sum_h W2[f,e,h]*relu(x[b,f]*W1[f,h]+b1[f,h])
// Piecewise-linear-in-x: per f, 65 segments; emb = A(seg)*x + C(seg).
// fp16 segment row (64B): 8 x {half2 A, half2 C}.
// Segment lookup: 512-bucket LUT (uchar2 bounds) + rare exact refinement.

#define BN 16384
#define FN 128
#define HN 64
#define EN 16
#define THR_S 72        // threshold stride (bank spread across ff)
#define TAB_S 524       // smem table stride in h4 units
#define NB   512        // buckets
#define LUT_S 520       // smem lut stride

#define BUCK_LO (-6.0f)
#define BUCK_SC ((float)NB / 12.0f)

struct __align__(8) h4 { __half2 a, c; };

__device__ h4     g_tab_h[FN * 520];    // per f: 65 segs * 8 h4
__device__ float  g_thr[FN * 64];       // sorted hinge thresholds per f
__device__ uchar2 g_lutp[FN * (NB + 1)]; // (lut[k], lut[k+1])

__device__ __forceinline__ int bucket_of(float v) {
    float p = (v - BUCK_LO) * BUCK_SC;
    p = fminf(fmaxf(p, 0.0f), (float)(NB - 1));
    return (int)p;
}

// ---------------------------------------------------------------------------
// Kernel 1: per-feature precompute. One block per f, 128 threads.
// ---------------------------------------------------------------------------
__global__ void __launch_bounds__(128) dfe_precompute(
    const float* __restrict__ W1, const float* __restrict__ b1,
    const float* __restrict__ W2, const float* __restrict__ b2)
{
    int f = blockIdx.x;
    int tid = threadIdx.x;

    __shared__ float sw[HN], sb[HN], tv_[HN], st[HN];
    __shared__ int   sidx[HN];
    __shared__ float sv[EN * HN];
    __shared__ float stab[65 * 32];

    for (int i = tid; i < EN * HN; i += 128) sv[i] = W2[f * EN * HN + i];

    if (tid < HN) {
        float w = W1[f * HN + tid];
        float b = b1[f * HN + tid];
        sw[tid] = w; sb[tid] = b;
        tv_[tid] = (w != 0.0f) ? (-b / w) : 3.0e38f;  // sentinel: never crossed
    }
    __syncthreads();

    // stable rank-sort of 64 thresholds
    if (tid < HN) {
        float tv = tv_[tid];
        int r = 0;
        for (int j = 0; j < HN; j++) {
            float tj = tv_[j];
            r += (tj < tv) || (tj == tv && j < tid);
        }
        st[r] = tv;
        sidx[r] = tid;
    }
    __syncthreads();

    if (tid < HN) g_thr[f * HN + tid] = st[tid];

    // LUT pairs: lut[k] = #{ thr : bucket(thr) < k }
    for (int k = tid; k <= NB; k += 128) {
        int c0 = 0, c1 = 0;
        for (int j = 0; j < HN; j++) {
            int bk = bucket_of(st[j]);
            c0 += (bk < k);
            c1 += (bk <= k);
        }
        g_lutp[f * (NB + 1) + k] = make_uchar2((unsigned char)c0, (unsigned char)c1);
    }

    // segment walk: 16 threads, one per e (all operands in smem)
    if (tid < EN) {
        int e = tid;
        const float* w2 = sv + e * HN;
        float A = 0.0f;
        float C = b2[f * EN + e];
        for (int h = 0; h < HN; h++) {
            float w = sw[h], b = sb[h], v = w2[h];
            float m = (w < 0.0f) ? 1.0f : 0.0f;            // active at x=-inf
            A += m * w * v;
            C += m * b * v;
            C += (w == 0.0f) ? fmaxf(b, 0.0f) * v : 0.0f;  // constant hinge
        }
        int grp = e >> 1, par = e & 1;
        for (int s = 0; s <= 64; s++) {
            stab[s * 32 + grp * 4 + par]     = A;
            stab[s * 32 + grp * 4 + 2 + par] = C;
            if (s < 64) {
                int h = sidx[s];
                float w = sw[h], b = sb[h], v = w2[h];
                float sg = (w > 0.0f) ? 1.0f : ((w < 0.0f) ? -1.0f : 0.0f);
                A += sg * w * v;
                C += sg * b * v;
            }
        }
    }
    __syncthreads();

    // pack fp32 staging -> fp16 table, coalesced writeback
    for (int i = tid; i < 520; i += 128) {
        int s = i >> 3, j = i & 7;
        const float* p = stab + s * 32 + j * 4;
        h4 v;
        v.a = __floats2half2_rn(p[0], p[1]);
        v.c = __floats2half2_rn(p[2], p[3]);
        g_tab_h[f * 520 + i] = v;
    }
}

// ---------------------------------------------------------------------------
// Kernel 2: evaluation. Block = 4 features ("quad") x 512 rows, 256 threads.
// Warp owns 64 rows as 8 batches of 8.
// Phase 1: lane=(ff=lane>>3, rrow=lane&7): 32 distinct lookups via 512-bucket
//   LUT (1 LDS.16) + rare exact refinement loop. Results exchanged through a
//   32-slot smem buffer. Phase 2: lane=(ff,j=lane&7): LDS.64 fp16 table chunk
//   -> 2 FMA -> coalesced float2 stcs (256B per row per warp).
// ---------------------------------------------------------------------------
__global__ void __launch_bounds__(256, 8) dfe_eval(
    const float* __restrict__ x, float* __restrict__ out)
{
    __shared__ h4     stab[4 * TAB_S];
    __shared__ float  sthr[4 * THR_S];
    __shared__ uchar2 slut[4 * LUT_S];
    __shared__ float2 sxch[8][32];     // per-warp (xs, seg) exchange

    int tid = threadIdx.x;
    int quad = blockIdx.x;
    int bbase = blockIdx.y * 512;

    #pragma unroll
    for (int ff = 0; ff < 4; ff++)
        for (int i = tid; i < 520; i += 256)
            stab[ff * TAB_S + i] = g_tab_h[(quad * 4 + ff) * 520 + i];
    for (int i = tid; i < 4 * 64; i += 256)
        sthr[(i >> 6) * THR_S + (i & 63)] = g_thr[quad * 256 + i];
    for (int i = tid; i < 4 * (NB + 1); i += 256) {
        int ff = i / (NB + 1), k = i % (NB + 1);
        slut[ff * LUT_S + k] = g_lutp[(quad * 4 + ff) * (NB + 1) + k];
    }
    __syncthreads();

    int lane = tid & 31, w = tid >> 5;
    int rrow = lane & 7;       // phase-1 row within batch
    int ff   = lane >> 3;      // feature within quad (both phases)
    int j    = lane & 7;       // phase-2 e-pair

    const float*  thrp = sthr + ff * THR_S;
    const uchar2* lutf = slut + ff * LUT_S;
    const h4*     tabf = stab + ff * TAB_S;
    float2*       xch  = sxch[w];

    int rb0 = bbase + w * 64;
    const float* xpb  = x   + (size_t)rb0 * FN + quad * 4 + ff;
    float*       outb = out + (size_t)rb0 * (FN * EN) + quad * 64 + ff * 16 + j * 2;

    auto seg_search = [&](float xs) -> int {
        int k = bucket_of(xs);
        uchar2 pr = lutf[k];
        int seg = pr.x;
        for (int t = pr.x; t < pr.y; t++) seg += (thrp[t] <= xs);
        return seg;   // exact count in [0,64]
    };

    float xs = __ldg(xpb + (size_t)rrow * FN);
    int   seg = seg_search(xs);

    #pragma unroll
    for (int batch = 0; batch < 8; batch++) {
        xch[lane] = make_float2(xs, __int_as_float(seg));
        __syncwarp();
        if (batch < 7)
            xs = __ldg(xpb + (size_t)((batch + 1) * 8 + rrow) * FN);

        float* orow = outb + (size_t)(batch * 8) * (FN * EN);
        #pragma unroll
        for (int r2 = 0; r2 < 8; r2++) {
            float2 e = xch[(lane & 24) | r2];   // slot of (rrow=r2, ff)
            int sg = __float_as_int(e.y);
            h4 v = tabf[sg * 8 + j];
            float2 a = __half22float2(v.a);
            float2 c = __half22float2(v.c);
            float2 o;
            o.x = fmaf(a.x, e.x, c.x);
            o.y = fmaf(a.y, e.x, c.y);
            __stcs((float2*)(orow + (size_t)r2 * (FN * EN)), o);
        }

        if (batch < 7) seg = seg_search(xs);
        __syncwarp();   // protect xch before next overwrite
    }
}

extern "C" void kernel_launch(void* const* d_in, const int* in_sizes, int n_in,
                              void* d_out, int out_size)
{
    const float* x  = (const float*)d_in[0];
    const float* W1 = (const float*)d_in[1];
    const float* b1 = (const float*)d_in[2];
    const float* W2 = (const float*)d_in[3];
    const float* b2 = (const float*)d_in[4];
    float* out = (float*)d_out;

    dfe_precompute<<<FN, 128>>>(W1, b1, W2, b2);
    dfe_eval<<<dim3(FN / 4, BN / 512), 256>>>(x, out);
}